// round 10
// baseline (speedup 1.0000x reference)
#include <cuda_runtime.h>
#include <cuda_bf16.h>
#include <cstdint>

#define N_NODES   100000
#define N_EDGES   1600000
#define N_WEIGHTS 256
#define D         16
#define SC_THREADS 512
#define SC_ITER   4
#define SC_CHUNK  (SC_THREADS * SC_ITER)  // 2048 edges per scatter block
#define MM_GRID_Y 10
#define BIN_CAP   8192

// ---------------- scratch ----------------
__device__ int   g_bin_fill[N_WEIGHTS];
__device__ int2  g_suv[N_WEIGHTS * BIN_CAP];
__device__ float g_acc[N_NODES * D];     // zero-initialized; re-zeroed by relu_k

// ---------------- helpers ----------------
__device__ __forceinline__ unsigned long long pack2(float lo, float hi) {
    unsigned long long r;
    asm("mov.b64 %0, {%1, %2};" : "=l"(r) : "f"(lo), "f"(hi));
    return r;
}
__device__ __forceinline__ void fma2(unsigned long long& d,
                                     unsigned long long a, unsigned long long b) {
    asm("fma.rn.f32x2 %0, %1, %2, %0;" : "+l"(d) : "l"(a), "l"(b));
}
__device__ __forceinline__ unsigned long long add2(unsigned long long a, unsigned long long b) {
    unsigned long long r;
    asm("add.rn.f32x2 %0, %1, %2;" : "=l"(r) : "l"(a), "l"(b));
    return r;
}
__device__ __forceinline__ void unpack2(unsigned long long v, float& lo, float& hi) {
    asm("mov.b64 {%0, %1}, %2;" : "=f"(lo), "=f"(hi) : "l"(v));
}
__device__ __forceinline__ void red_add_v4(float* p, float a, float b, float c, float d) {
    asm volatile("red.global.add.v4.f32 [%0], {%1, %2, %3, %4};"
                 :: "l"(p), "f"(a), "f"(b), "f"(c), "f"(d) : "memory");
}

// ---------------- kernels ----------------

__global__ void fill_init_k() {
    int t = threadIdx.x;
    g_bin_fill[t] = t * BIN_CAP;
}

// Counting-sort scatter: 512 threads, 4 consecutive edges each (shorter atomic chains).
__global__ void __launch_bounds__(SC_THREADS)
scatter_k(const int* __restrict__ u, const int* __restrict__ v,
          const int* __restrict__ widx, int E) {
    __shared__ int  cnt[N_WEIGHTS];
    __shared__ int  lstart[N_WEIGHTS];
    __shared__ int  gbase[N_WEIGHTS];
    __shared__ int  wsum[8];
    __shared__ int2 sval[SC_CHUNK];
    __shared__ unsigned char sbin[SC_CHUNK];

    const int tid  = threadIdx.x;
    const int lane = tid & 31;
    const int wrp  = tid >> 5;
    const int blk0 = blockIdx.x * SC_CHUNK;
    if (blk0 >= E) return;
    const int n = min(SC_CHUNK, E - blk0);

    if (tid < N_WEIGHTS) cnt[tid] = 0;
    __syncthreads();

    const int e0 = blk0 + tid * SC_ITER;
    const bool act = (e0 < E);     // E % 4 == 0 -> all-in or all-out

    int eu[SC_ITER], ev[SC_ITER], ew[SC_ITER], er[SC_ITER];
    if (act) {
        int4 ua = *(const int4*)(u + e0);
        int4 va = *(const int4*)(v + e0);
        int4 wa = *(const int4*)(widx + e0);
        eu[0]=ua.x; eu[1]=ua.y; eu[2]=ua.z; eu[3]=ua.w;
        ev[0]=va.x; ev[1]=va.y; ev[2]=va.z; ev[3]=va.w;
        ew[0]=wa.x; ew[1]=wa.y; ew[2]=wa.z; ew[3]=wa.w;
#pragma unroll
        for (int i = 0; i < SC_ITER; i++)
            er[i] = atomicAdd(&cnt[ew[i]], 1);
    }
    __syncthreads();

    // exclusive scan of cnt[256] by the first 256 threads (shuffle-based)
    if (tid < N_WEIGHTS) {
        const int c = cnt[tid];
        int s = c;
#pragma unroll
        for (int off = 1; off < 32; off <<= 1) {
            int t = __shfl_up_sync(0xffffffffu, s, off);
            if (lane >= off) s += t;
        }
        if (lane == 31) wsum[wrp] = s;
        __syncthreads();
        if (wrp == 0 && lane < 8) {
            int t = wsum[lane];
#pragma unroll
            for (int off = 1; off < 8; off <<= 1) {
                int q = __shfl_up_sync(0xffu, t, off);
                if (lane >= off) t += q;
            }
            wsum[lane] = t;
        }
        __syncthreads();
        int incl = s + (wrp ? wsum[wrp - 1] : 0);
        lstart[tid] = incl - c;
        gbase[tid]  = c ? atomicAdd(&g_bin_fill[tid], c) : 0;
    } else {
        __syncthreads();
        __syncthreads();
    }
    __syncthreads();

    if (act) {
#pragma unroll
        for (int i = 0; i < SC_ITER; i++) {
            int b = ew[i];
            int slot = lstart[b] + er[i];
            sval[slot] = make_int2(eu[i], ev[i]);
            sbin[slot] = (unsigned char)b;
        }
    }
    __syncthreads();

    for (int s = tid; s < n; s += SC_THREADS) {
        int b = sbin[s];
        g_suv[gbase[b] + (s - lstart[b])] = sval[s];
    }
}

// Smem-free edge kernel: transposed partial compute + shfl butterfly reduction.
// Lane (el, q): loads x quarter q of edge el, computes partials of ALL 16 outputs
// against W columns [4q, 4q+4), butterfly-reduces across the 4 lanes of the edge,
// ends holding outputs [4q, 4q+4) -> one red.v4.
__global__ void __launch_bounds__(256)
edge_mm_k(const float* __restrict__ x, const float* __restrict__ W,
          float* __restrict__ out) {
    const int w  = blockIdx.x;
    const int bs = w * BIN_CAP;
    const int be = g_bin_fill[w];

    const int tid  = threadIdx.x;
    const int lane = tid & 31;
    const int wid  = tid >> 5;
    const int q    = lane & 3;      // x quarter / W column group / output group
    const int el   = lane >> 2;     // edge slot 0..7

    // W columns [4q, 4q+4), all 16 rows, packed as row-pairs:
    // wp[k][r2] = (W[2r2][4q+k], W[2r2+1][4q+k])
    const float* Wb = W + (size_t)w * (D * D);
    unsigned long long wp[4][8];
#pragma unroll
    for (int k = 0; k < 4; k++)
#pragma unroll
        for (int r2 = 0; r2 < 8; r2++)
            wp[k][r2] = pack2(Wb[(2 * r2) * D + 4 * q + k],
                              Wb[(2 * r2 + 1) * D + 4 * q + k]);

    const float4* x4 = (const float4*)x;
    const int gw   = blockIdx.y * 8 + wid;
    const int step = gridDim.y * 8 * 8;       // warps * 8 edges

    int e0 = bs + gw * 8;
    if (e0 >= be) return;

    // pipeline: uv for iters i, i+1; x for iter i
    int2 uv0 = (e0 + el        < be) ? g_suv[e0 + el]        : make_int2(0, 0);
    int2 uv1 = (e0 + step + el < be) ? g_suv[e0 + step + el] : make_int2(0, 0);
    float4 xq = x4[(size_t)uv0.x * 4 + q];

    for (; e0 < be; e0 += step) {
        const bool p0 = (e0 + el < be);

        const int e2 = e0 + 2 * step;
        int2 uv2 = (e2 + el < be) ? g_suv[e2 + el] : make_int2(0, 0);
        float4 xn = x4[(size_t)uv1.x * 4 + q];

        // partials for all 16 outputs (8 f32x2 accumulators)
        unsigned long long acc[8];
        {
            unsigned long long b0 = pack2(xq.x, xq.x);
            unsigned long long b1 = pack2(xq.y, xq.y);
            unsigned long long b2 = pack2(xq.z, xq.z);
            unsigned long long b3 = pack2(xq.w, xq.w);
#pragma unroll
            for (int r2 = 0; r2 < 8; r2++) {
                unsigned long long a = 0ull;
                fma2(a, wp[0][r2], b0);
                fma2(a, wp[1][r2], b1);
                fma2(a, wp[2][r2], b2);
                fma2(a, wp[3][r2], b3);
                acc[r2] = a;
            }
        }

        // butterfly round 1 (xor 2): q<2 keeps acc[0..4), q>=2 keeps acc[4..8)
        const bool lowHalf = (q < 2);
#pragma unroll
        for (int j = 0; j < 4; j++) {
            unsigned long long src = lowHalf ? acc[4 + j] : acc[j];
            unsigned long long got = __shfl_xor_sync(0xffffffffu, src, 2);
            if (lowHalf) acc[j]     = add2(acc[j], got);
            else         acc[4 + j] = add2(acc[4 + j], got);
        }
        // butterfly round 2 (xor 1): even q keeps first 2 of its half
        const int base = lowHalf ? 0 : 4;
        const bool lowPair = ((q & 1) == 0);
#pragma unroll
        for (int j = 0; j < 2; j++) {
            unsigned long long src = lowPair ? acc[base + 2 + j] : acc[base + j];
            unsigned long long got = __shfl_xor_sync(0xffffffffu, src, 1);
            if (lowPair) acc[base + j]     = add2(acc[base + j], got);
            else         acc[base + 2 + j] = add2(acc[base + 2 + j], got);
        }

        if (p0) {
            const int kb = 4 * (q >> 1) + 2 * (q & 1);   // my kept u64 pair
            float r0, r1, r2, r3;
            unpack2(acc[kb],     r0, r1);
            unpack2(acc[kb + 1], r2, r3);
            red_add_v4(out + (size_t)uv0.y * D + 4 * q, r0, r1, r2, r3);
        }

        uv0 = uv1;
        uv1 = uv2;
        xq  = xn;
    }
}

// relu: reads accumulator, writes output, re-zeroes accumulator for next replay.
__global__ void __launch_bounds__(512)
relu_k(float* __restrict__ out, int n4) {
    const float4 z = make_float4(0.f, 0.f, 0.f, 0.f);
    float4* a4 = (float4*)g_acc;
    float4* o4 = (float4*)out;
    int i = blockIdx.x * 1024 + threadIdx.x;
#pragma unroll
    for (int rep = 0; rep < 2; rep++, i += 512) {
        if (i < n4) {
            float4 v = a4[i];
            v.x = fmaxf(v.x, 0.f);
            v.y = fmaxf(v.y, 0.f);
            v.z = fmaxf(v.z, 0.f);
            v.w = fmaxf(v.w, 0.f);
            o4[i] = v;
            a4[i] = z;
        }
    }
}

// ---------------- launcher ----------------
extern "C" void kernel_launch(void* const* d_in, const int* in_sizes, int n_in,
                              void* d_out, int out_size) {
    const float* x    = (const float*)d_in[0];
    const float* W    = (const float*)d_in[1];
    const int*   u    = (const int*)d_in[2];
    const int*   v    = (const int*)d_in[3];
    const int*   widx = (const int*)d_in[4];
    float* out = (float*)d_out;

    const int E = in_sizes[2];

    float* acc;
    cudaGetSymbolAddress((void**)&acc, g_acc);

    fill_init_k<<<1, 256>>>();
    scatter_k<<<(E + SC_CHUNK - 1) / SC_CHUNK, SC_THREADS>>>(u, v, widx, E);
    edge_mm_k<<<dim3(N_WEIGHTS, MM_GRID_Y), 256>>>(x, W, acc);
    int n4 = out_size / 4;
    relu_k<<<(n4 + 1023) / 1024, 512>>>(out, n4);
}

// round 11
// speedup vs baseline: 2.9902x; 2.9902x over previous
#include <cuda_runtime.h>
#include <cuda_bf16.h>
#include <cstdint>

#define N_NODES   100000
#define N_EDGES   1600000
#define N_WEIGHTS 256
#define D         16
#define SC_ITER   8
#define SC_CHUNK  (256 * SC_ITER)   // 2048 edges per scatter block
#define MM_GRID_Y 10
#define BIN_CAP   8192

// ---------------- scratch (persistent across graph replays) ----------------
__device__ int   g_bin_fill[N_WEIGHTS];          // per-bin COUNT; zero at load, re-zeroed by relu_k
__device__ int2  g_suv[N_WEIGHTS * BIN_CAP];
__device__ float g_acc[N_NODES * D];             // zero at load, re-zeroed by relu_k

// ---------------- helpers ----------------
__device__ __forceinline__ unsigned long long pack2(float lo, float hi) {
    unsigned long long r;
    asm("mov.b64 %0, {%1, %2};" : "=l"(r) : "f"(lo), "f"(hi));
    return r;
}
__device__ __forceinline__ void fma2(unsigned long long& d,
                                     unsigned long long a, unsigned long long b) {
    asm("fma.rn.f32x2 %0, %1, %2, %0;" : "+l"(d) : "l"(a), "l"(b));
}
__device__ __forceinline__ void unpack2(unsigned long long v, float& lo, float& hi) {
    asm("mov.b64 {%0, %1}, %2;" : "=f"(lo), "=f"(hi) : "l"(v));
}
__device__ __forceinline__ void red_add_v4(float* p, float a, float b, float c, float d) {
    asm volatile("red.global.add.v4.f32 [%0], {%1, %2, %3, %4};"
                 :: "l"(p), "f"(a), "f"(b), "f"(c), "f"(d) : "memory");
}

// ---------------- kernels ----------------

// One-pass counting-sort scatter into bump-allocated bin regions.
// g_bin_fill holds counts (base 0); region base = w * BIN_CAP.
__global__ void __launch_bounds__(256)
scatter_k(const int* __restrict__ u, const int* __restrict__ v,
          const int* __restrict__ widx, int E) {
    __shared__ int  cnt[N_WEIGHTS];
    __shared__ int  lstart[N_WEIGHTS];
    __shared__ int  gbase[N_WEIGHTS];
    __shared__ int  wsum[8];
    __shared__ int2 sval[SC_CHUNK];
    __shared__ unsigned char sbin[SC_CHUNK];

    const int tid  = threadIdx.x;
    const int lane = tid & 31;
    const int wrp  = tid >> 5;
    const int blk0 = blockIdx.x * SC_CHUNK;
    if (blk0 >= E) return;
    const int n = min(SC_CHUNK, E - blk0);

    cnt[tid] = 0;
    __syncthreads();

    const int e0 = blk0 + tid * SC_ITER;
    const bool act = (e0 < E);   // E % 8 == 0 -> all-in or all-out

    int eu[SC_ITER], ev[SC_ITER], ew[SC_ITER], er[SC_ITER];
    if (act) {
        const int4* u4 = (const int4*)(u + e0);
        const int4* v4 = (const int4*)(v + e0);
        const int4* w4 = (const int4*)(widx + e0);
        int4 ua = u4[0], ub = u4[1];
        int4 va = v4[0], vb = v4[1];
        int4 wa = w4[0], wb = w4[1];
        eu[0]=ua.x; eu[1]=ua.y; eu[2]=ua.z; eu[3]=ua.w;
        eu[4]=ub.x; eu[5]=ub.y; eu[6]=ub.z; eu[7]=ub.w;
        ev[0]=va.x; ev[1]=va.y; ev[2]=va.z; ev[3]=va.w;
        ev[4]=vb.x; ev[5]=vb.y; ev[6]=vb.z; ev[7]=vb.w;
        ew[0]=wa.x; ew[1]=wa.y; ew[2]=wa.z; ew[3]=wa.w;
        ew[4]=wb.x; ew[5]=wb.y; ew[6]=wb.z; ew[7]=wb.w;
#pragma unroll
        for (int i = 0; i < SC_ITER; i++)
            er[i] = atomicAdd(&cnt[ew[i]], 1);
    }
    __syncthreads();

    // shuffle-based exclusive block scan of cnt[256]
    {
        const int c = cnt[tid];
        int s = c;
#pragma unroll
        for (int off = 1; off < 32; off <<= 1) {
            int t = __shfl_up_sync(0xffffffffu, s, off);
            if (lane >= off) s += t;
        }
        if (lane == 31) wsum[wrp] = s;
        __syncthreads();
        if (wrp == 0 && lane < 8) {
            int t = wsum[lane];
#pragma unroll
            for (int off = 1; off < 8; off <<= 1) {
                int q = __shfl_up_sync(0xffu, t, off);
                if (lane >= off) t += q;
            }
            wsum[lane] = t;
        }
        __syncthreads();
        int incl = s + (wrp ? wsum[wrp - 1] : 0);
        lstart[tid] = incl - c;
        gbase[tid]  = tid * BIN_CAP + (c ? atomicAdd(&g_bin_fill[tid], c) : 0);
    }
    __syncthreads();

    if (act) {
#pragma unroll
        for (int i = 0; i < SC_ITER; i++) {
            int b = ew[i];
            int slot = lstart[b] + er[i];
            sval[slot] = make_int2(eu[i], ev[i]);
            sbin[slot] = (unsigned char)b;
        }
    }
    __syncthreads();

    for (int s = tid; s < n; s += 256) {
        int b = sbin[s];
        g_suv[gbase[b] + (s - lstart[b])] = sval[s];
    }
}

// Warp-autonomous edge kernel; uv prefetched 2 iters ahead, x 1 iter ahead.
__global__ void __launch_bounds__(256)
edge_mm_k(const float* __restrict__ x, const float* __restrict__ W,
          float* __restrict__ out) {
    const int w  = blockIdx.x;
    const int bs = w * BIN_CAP;
    const int be = bs + g_bin_fill[w];   // count-based

    const int tid   = threadIdx.x;
    const int lane  = tid & 31;
    const int wid   = tid >> 5;
    const int qrt   = lane & 3;
    const int el    = lane >> 2;
    const int obase = qrt * 4;

    const float* Wb = W + (size_t)w * (D * D);
    unsigned long long wp0[D], wp1[D];
#pragma unroll
    for (int k = 0; k < D; k++) {
        wp0[k] = pack2(Wb[(obase + 0) * D + k], Wb[(obase + 1) * D + k]);
        wp1[k] = pack2(Wb[(obase + 2) * D + k], Wb[(obase + 3) * D + k]);
    }

    __shared__ float4 xs[8][16 * 5];

    const float4* x4 = (const float4*)x;
    const int gw   = blockIdx.y * 8 + wid;
    const int step = gridDim.y * 8 * 16;

    int e0 = bs + gw * 16;
    if (e0 >= be) return;

    int2 uv0A = (e0 + el     < be) ? g_suv[e0 + el]     : make_int2(0, 0);
    int2 uv0B = (e0 + 8 + el < be) ? g_suv[e0 + 8 + el] : make_int2(0, 0);
    int2 uv1A = (e0 + step + el     < be) ? g_suv[e0 + step + el]     : make_int2(0, 0);
    int2 uv1B = (e0 + step + 8 + el < be) ? g_suv[e0 + step + 8 + el] : make_int2(0, 0);
    float4 xqA = x4[(size_t)uv0A.x * 4 + qrt];
    float4 xqB = x4[(size_t)uv0B.x * 4 + qrt];

    for (; e0 < be; e0 += step) {
        const bool pA = (e0 + el     < be);
        const bool pB = (e0 + 8 + el < be);

        const int e2 = e0 + 2 * step;
        int2 uv2A = (e2 + el     < be) ? g_suv[e2 + el]     : make_int2(0, 0);
        int2 uv2B = (e2 + 8 + el < be) ? g_suv[e2 + 8 + el] : make_int2(0, 0);

        float4 xnA = x4[(size_t)uv1A.x * 4 + qrt];
        float4 xnB = x4[(size_t)uv1B.x * 4 + qrt];

        xs[wid][el * 5 + qrt]       = xqA;
        xs[wid][(8 + el) * 5 + qrt] = xqB;
        __syncwarp();

        unsigned long long a0A = 0ull, a1A = 0ull, a0B = 0ull, a1B = 0ull;
#pragma unroll
        for (int q = 0; q < 4; q++) {
            float4 xA = xs[wid][el * 5 + q];
            float4 xB = xs[wid][(8 + el) * 5 + q];
            unsigned long long bA0 = pack2(xA.x, xA.x), bB0 = pack2(xB.x, xB.x);
            unsigned long long bA1 = pack2(xA.y, xA.y), bB1 = pack2(xB.y, xB.y);
            unsigned long long bA2 = pack2(xA.z, xA.z), bB2 = pack2(xB.z, xB.z);
            unsigned long long bA3 = pack2(xA.w, xA.w), bB3 = pack2(xB.w, xB.w);
            fma2(a0A, wp0[q * 4 + 0], bA0);  fma2(a1A, wp1[q * 4 + 0], bA0);
            fma2(a0B, wp0[q * 4 + 0], bB0);  fma2(a1B, wp1[q * 4 + 0], bB0);
            fma2(a0A, wp0[q * 4 + 1], bA1);  fma2(a1A, wp1[q * 4 + 1], bA1);
            fma2(a0B, wp0[q * 4 + 1], bB1);  fma2(a1B, wp1[q * 4 + 1], bB1);
            fma2(a0A, wp0[q * 4 + 2], bA2);  fma2(a1A, wp1[q * 4 + 2], bA2);
            fma2(a0B, wp0[q * 4 + 2], bB2);  fma2(a1B, wp1[q * 4 + 2], bB2);
            fma2(a0A, wp0[q * 4 + 3], bA3);  fma2(a1A, wp1[q * 4 + 3], bA3);
            fma2(a0B, wp0[q * 4 + 3], bB3);  fma2(a1B, wp1[q * 4 + 3], bB3);
        }

        if (pA) {
            float r0, r1, r2, r3;
            unpack2(a0A, r0, r1);
            unpack2(a1A, r2, r3);
            red_add_v4(out + (size_t)uv0A.y * D + obase, r0, r1, r2, r3);
        }
        if (pB) {
            float r0, r1, r2, r3;
            unpack2(a0B, r0, r1);
            unpack2(a1B, r2, r3);
            red_add_v4(out + (size_t)uv0B.y * D + obase, r0, r1, r2, r3);
        }
        __syncwarp();

        uv0A = uv1A;  uv0B = uv1B;
        uv1A = uv2A;  uv1B = uv2B;
        xqA  = xnA;   xqB  = xnB;
    }
}

// relu: read accumulator -> write output; re-zero accumulator and bin counts
// for the next graph replay.
__global__ void __launch_bounds__(256)
relu_k(float* __restrict__ out, int n4) {
    int i = blockIdx.x * blockDim.x + threadIdx.x;
    if (i < n4) {
        float4* a4 = (float4*)g_acc;
        float4 v = a4[i];
        v.x = fmaxf(v.x, 0.f);
        v.y = fmaxf(v.y, 0.f);
        v.z = fmaxf(v.z, 0.f);
        v.w = fmaxf(v.w, 0.f);
        ((float4*)out)[i] = v;
        a4[i] = make_float4(0.f, 0.f, 0.f, 0.f);
    }
    if (blockIdx.x == 0 && threadIdx.x < N_WEIGHTS)
        g_bin_fill[threadIdx.x] = 0;
}

// ---------------- launcher ----------------
extern "C" void kernel_launch(void* const* d_in, const int* in_sizes, int n_in,
                              void* d_out, int out_size) {
    const float* x    = (const float*)d_in[0];
    const float* W    = (const float*)d_in[1];
    const int*   u    = (const int*)d_in[2];
    const int*   v    = (const int*)d_in[3];
    const int*   widx = (const int*)d_in[4];
    float* out = (float*)d_out;

    const int E = in_sizes[2];

    float* acc;
    cudaGetSymbolAddress((void**)&acc, g_acc);

    scatter_k<<<(E + SC_CHUNK - 1) / SC_CHUNK, 256>>>(u, v, widx, E);
    edge_mm_k<<<dim3(N_WEIGHTS, MM_GRID_Y), 256>>>(x, W, acc);
    int n4 = out_size / 4;
    relu_k<<<(n4 + 255) / 256, 256>>>(out, n4);
}

// round 12
// speedup vs baseline: 3.3219x; 1.1109x over previous
#include <cuda_runtime.h>
#include <cuda_bf16.h>
#include <cstdint>

#define N_NODES   100000
#define N_EDGES   1600000
#define N_WEIGHTS 256
#define D         16
#define SC_ITER   8
#define SC_CHUNK  (256 * SC_ITER)   // 2048 edges per scatter block
#define MM_GRID_Y 5
#define BIN_CAP   8192

// ---------------- scratch (persistent across graph replays) ----------------
__device__ int   g_bin_fill[N_WEIGHTS];   // per-bin COUNT; zero at load, re-zeroed by relu_k
__device__ int2  g_suv[N_WEIGHTS * BIN_CAP];
__device__ float g_acc[N_NODES * D];      // zero at load, re-zeroed by relu_k

// ---------------- helpers ----------------
__device__ __forceinline__ unsigned long long pack2(float lo, float hi) {
    unsigned long long r;
    asm("mov.b64 %0, {%1, %2};" : "=l"(r) : "f"(lo), "f"(hi));
    return r;
}
__device__ __forceinline__ void fma2(unsigned long long& d,
                                     unsigned long long a, unsigned long long b) {
    asm("fma.rn.f32x2 %0, %1, %2, %0;" : "+l"(d) : "l"(a), "l"(b));
}
__device__ __forceinline__ void unpack2(unsigned long long v, float& lo, float& hi) {
    asm("mov.b64 {%0, %1}, %2;" : "=f"(lo), "=f"(hi) : "l"(v));
}
__device__ __forceinline__ void red_add_v4(float* p, float a, float b, float c, float d) {
    asm volatile("red.global.add.v4.f32 [%0], {%1, %2, %3, %4};"
                 :: "l"(p), "f"(a), "f"(b), "f"(c), "f"(d) : "memory");
}

// ---------------- kernels ----------------

// One-pass counting-sort scatter into bump-allocated bin regions.
__global__ void __launch_bounds__(256)
scatter_k(const int* __restrict__ u, const int* __restrict__ v,
          const int* __restrict__ widx, int E) {
    __shared__ int  cnt[N_WEIGHTS];
    __shared__ int  lstart[N_WEIGHTS];
    __shared__ int  gbase[N_WEIGHTS];
    __shared__ int  wsum[8];
    __shared__ int2 sval[SC_CHUNK];
    __shared__ unsigned char sbin[SC_CHUNK];

    const int tid  = threadIdx.x;
    const int lane = tid & 31;
    const int wrp  = tid >> 5;
    const int blk0 = blockIdx.x * SC_CHUNK;
    if (blk0 >= E) return;
    const int n = min(SC_CHUNK, E - blk0);

    cnt[tid] = 0;
    __syncthreads();

    const int e0 = blk0 + tid * SC_ITER;
    const bool act = (e0 < E);

    int eu[SC_ITER], ev[SC_ITER], ew[SC_ITER], er[SC_ITER];
    if (act) {
        const int4* u4 = (const int4*)(u + e0);
        const int4* v4 = (const int4*)(v + e0);
        const int4* w4 = (const int4*)(widx + e0);
        int4 ua = u4[0], ub = u4[1];
        int4 va = v4[0], vb = v4[1];
        int4 wa = w4[0], wb = w4[1];
        eu[0]=ua.x; eu[1]=ua.y; eu[2]=ua.z; eu[3]=ua.w;
        eu[4]=ub.x; eu[5]=ub.y; eu[6]=ub.z; eu[7]=ub.w;
        ev[0]=va.x; ev[1]=va.y; ev[2]=va.z; ev[3]=va.w;
        ev[4]=vb.x; ev[5]=vb.y; ev[6]=vb.z; ev[7]=vb.w;
        ew[0]=wa.x; ew[1]=wa.y; ew[2]=wa.z; ew[3]=wa.w;
        ew[4]=wb.x; ew[5]=wb.y; ew[6]=wb.z; ew[7]=wb.w;
#pragma unroll
        for (int i = 0; i < SC_ITER; i++)
            er[i] = atomicAdd(&cnt[ew[i]], 1);
    }
    __syncthreads();

    {
        const int c = cnt[tid];
        int s = c;
#pragma unroll
        for (int off = 1; off < 32; off <<= 1) {
            int t = __shfl_up_sync(0xffffffffu, s, off);
            if (lane >= off) s += t;
        }
        if (lane == 31) wsum[wrp] = s;
        __syncthreads();
        if (wrp == 0 && lane < 8) {
            int t = wsum[lane];
#pragma unroll
            for (int off = 1; off < 8; off <<= 1) {
                int q = __shfl_up_sync(0xffu, t, off);
                if (lane >= off) t += q;
            }
            wsum[lane] = t;
        }
        __syncthreads();
        int incl = s + (wrp ? wsum[wrp - 1] : 0);
        lstart[tid] = incl - c;
        gbase[tid]  = tid * BIN_CAP + (c ? atomicAdd(&g_bin_fill[tid], c) : 0);
    }
    __syncthreads();

    if (act) {
#pragma unroll
        for (int i = 0; i < SC_ITER; i++) {
            int b = ew[i];
            int slot = lstart[b] + er[i];
            sval[slot] = make_int2(eu[i], ev[i]);
            sbin[slot] = (unsigned char)b;
        }
    }
    __syncthreads();

    for (int s = tid; s < n; s += 256) {
        int b = sbin[s];
        g_suv[gbase[b] + (s - lstart[b])] = sval[s];
    }
}

// Warp-autonomous edge kernel: 32 edges per warp-iteration (4 groups),
// uv prefetched one iteration ahead.
__global__ void __launch_bounds__(256)
edge_mm_k(const float* __restrict__ x, const float* __restrict__ W,
          float* __restrict__ out) {
    const int w  = blockIdx.x;
    const int bs = w * BIN_CAP;
    const int be = bs + g_bin_fill[w];

    const int tid   = threadIdx.x;
    const int lane  = tid & 31;
    const int wid   = tid >> 5;
    const int qrt   = lane & 3;
    const int el    = lane >> 2;
    const int obase = qrt * 4;

    // W rows [obase, obase+4) via float4 loads, packed as f32x2 row pairs
    const float4* Wp = (const float4*)(W + (size_t)w * (D * D));
    unsigned long long wp0[D], wp1[D];
    {
        float4 r0[4], r1[4], r2[4], r3[4];
#pragma unroll
        for (int qq = 0; qq < 4; qq++) {
            r0[qq] = Wp[(obase + 0) * 4 + qq];
            r1[qq] = Wp[(obase + 1) * 4 + qq];
            r2[qq] = Wp[(obase + 2) * 4 + qq];
            r3[qq] = Wp[(obase + 3) * 4 + qq];
        }
#pragma unroll
        for (int qq = 0; qq < 4; qq++) {
            wp0[qq * 4 + 0] = pack2(r0[qq].x, r1[qq].x);
            wp0[qq * 4 + 1] = pack2(r0[qq].y, r1[qq].y);
            wp0[qq * 4 + 2] = pack2(r0[qq].z, r1[qq].z);
            wp0[qq * 4 + 3] = pack2(r0[qq].w, r1[qq].w);
            wp1[qq * 4 + 0] = pack2(r2[qq].x, r3[qq].x);
            wp1[qq * 4 + 1] = pack2(r2[qq].y, r3[qq].y);
            wp1[qq * 4 + 2] = pack2(r2[qq].z, r3[qq].z);
            wp1[qq * 4 + 3] = pack2(r2[qq].w, r3[qq].w);
        }
    }

    // 32 edges * 5-float4 stride per warp = 2560B; 8 warps = 20KB
    __shared__ float4 xs[8][32 * 5];

    const float4* x4 = (const float4*)x;
    const int gw   = blockIdx.y * 8 + wid;
    const int step = gridDim.y * 8 * 32;

    int e0 = bs + gw * 32;
    if (e0 >= be) return;

    int2 uv0[4], uv1[4];
#pragma unroll
    for (int g = 0; g < 4; g++) {
        int e = e0 + g * 8 + el;
        uv0[g] = (e < be) ? g_suv[e] : make_int2(0, 0);
        int en = e + step;
        uv1[g] = (en < be) ? g_suv[en] : make_int2(0, 0);
    }

    for (; e0 < be; e0 += step) {
        // x loads for current 4 groups (uv resident)
        float4 xq[4];
#pragma unroll
        for (int g = 0; g < 4; g++)
            xq[g] = x4[(size_t)uv0[g].x * 4 + qrt];

        // prefetch uv for iter i+2
        int2 uv2[4];
        const int e2 = e0 + 2 * step;
#pragma unroll
        for (int g = 0; g < 4; g++) {
            int e = e2 + g * 8 + el;
            uv2[g] = (e < be) ? g_suv[e] : make_int2(0, 0);
        }

#pragma unroll
        for (int g = 0; g < 4; g++)
            xs[wid][(g * 8 + el) * 5 + qrt] = xq[g];
        __syncwarp();

        unsigned long long a0[4] = {0ull, 0ull, 0ull, 0ull};
        unsigned long long a1[4] = {0ull, 0ull, 0ull, 0ull};
#pragma unroll
        for (int q = 0; q < 4; q++) {
#pragma unroll
            for (int g = 0; g < 4; g++) {
                float4 xv = xs[wid][(g * 8 + el) * 5 + q];
                unsigned long long b0 = pack2(xv.x, xv.x);
                unsigned long long b1 = pack2(xv.y, xv.y);
                unsigned long long b2 = pack2(xv.z, xv.z);
                unsigned long long b3 = pack2(xv.w, xv.w);
                fma2(a0[g], wp0[q * 4 + 0], b0);  fma2(a1[g], wp1[q * 4 + 0], b0);
                fma2(a0[g], wp0[q * 4 + 1], b1);  fma2(a1[g], wp1[q * 4 + 1], b1);
                fma2(a0[g], wp0[q * 4 + 2], b2);  fma2(a1[g], wp1[q * 4 + 2], b2);
                fma2(a0[g], wp0[q * 4 + 3], b3);  fma2(a1[g], wp1[q * 4 + 3], b3);
            }
        }

#pragma unroll
        for (int g = 0; g < 4; g++) {
            if (e0 + g * 8 + el < be) {
                float r0, r1, r2, r3;
                unpack2(a0[g], r0, r1);
                unpack2(a1[g], r2, r3);
                red_add_v4(out + (size_t)uv0[g].y * D + obase, r0, r1, r2, r3);
            }
        }
        __syncwarp();

#pragma unroll
        for (int g = 0; g < 4; g++) {
            uv0[g] = uv1[g];
            uv1[g] = uv2[g];
        }
    }
}

// relu: read accumulator -> write output; re-zero accumulator and bin counts.
__global__ void __launch_bounds__(256)
relu_k(float* __restrict__ out, int n4) {
    int i = blockIdx.x * blockDim.x + threadIdx.x;
    if (i < n4) {
        float4* a4 = (float4*)g_acc;
        float4 v = a4[i];
        v.x = fmaxf(v.x, 0.f);
        v.y = fmaxf(v.y, 0.f);
        v.z = fmaxf(v.z, 0.f);
        v.w = fmaxf(v.w, 0.f);
        ((float4*)out)[i] = v;
        a4[i] = make_float4(0.f, 0.f, 0.f, 0.f);
    }
    if (blockIdx.x == 0 && threadIdx.x < N_WEIGHTS)
        g_bin_fill[threadIdx.x] = 0;
}

// ---------------- launcher ----------------
extern "C" void kernel_launch(void* const* d_in, const int* in_sizes, int n_in,
                              void* d_out, int out_size) {
    const float* x    = (const float*)d_in[0];
    const float* W    = (const float*)d_in[1];
    const int*   u    = (const int*)d_in[2];
    const int*   v    = (const int*)d_in[3];
    const int*   widx = (const int*)d_in[4];
    float* out = (float*)d_out;

    const int E = in_sizes[2];

    float* acc;
    cudaGetSymbolAddress((void**)&acc, g_acc);

    scatter_k<<<(E + SC_CHUNK - 1) / SC_CHUNK, 256>>>(u, v, widx, E);
    edge_mm_k<<<dim3(N_WEIGHTS, MM_GRID_Y), 256>>>(x, W, acc);
    int n4 = out_size / 4;
    relu_k<<<(n4 + 255) / 256, 256>>>(out, n4);
}

// round 13
// speedup vs baseline: 3.3995x; 1.0233x over previous
#include <cuda_runtime.h>
#include <cuda_bf16.h>
#include <cstdint>

#define N_NODES   100000
#define N_EDGES   1600000
#define N_WEIGHTS 256
#define D         16
#define SC_THREADS 512
#define SC_ITER   4
#define SC_CHUNK  (SC_THREADS * SC_ITER)   // 2048 edges per scatter block
#define MM_GRID_Y 5
#define BIN_CAP   8192

// ---------------- scratch (persistent across graph replays) ----------------
__device__ int   g_bin_fill[N_WEIGHTS];   // per-bin COUNT; zero at load, re-zeroed by relu_k
__device__ int2  g_suv[N_WEIGHTS * BIN_CAP];
__device__ float g_acc[N_NODES * D];      // zero at load, re-zeroed by relu_k

// ---------------- helpers ----------------
__device__ __forceinline__ unsigned long long pack2(float lo, float hi) {
    unsigned long long r;
    asm("mov.b64 %0, {%1, %2};" : "=l"(r) : "f"(lo), "f"(hi));
    return r;
}
__device__ __forceinline__ void fma2(unsigned long long& d,
                                     unsigned long long a, unsigned long long b) {
    asm("fma.rn.f32x2 %0, %1, %2, %0;" : "+l"(d) : "l"(a), "l"(b));
}
__device__ __forceinline__ void unpack2(unsigned long long v, float& lo, float& hi) {
    asm("mov.b64 {%0, %1}, %2;" : "=f"(lo), "=f"(hi) : "l"(v));
}
__device__ __forceinline__ void red_add_v4(float* p, float a, float b, float c, float d) {
    asm volatile("red.global.add.v4.f32 [%0], {%1, %2, %3, %4};"
                 :: "l"(p), "f"(a), "f"(b), "f"(c), "f"(d) : "memory");
}

// ---------------- kernels ----------------

// One-pass counting-sort scatter into bump-allocated bin regions.
// 512 threads x 4 consecutive edges: shorter serial rank-atomic chains.
__global__ void __launch_bounds__(SC_THREADS)
scatter_k(const int* __restrict__ u, const int* __restrict__ v,
          const int* __restrict__ widx, int E) {
    __shared__ int  cnt[N_WEIGHTS];
    __shared__ int  lstart[N_WEIGHTS];
    __shared__ int  gbase[N_WEIGHTS];
    __shared__ int  wsum[8];
    __shared__ int2 sval[SC_CHUNK];
    __shared__ unsigned char sbin[SC_CHUNK];

    const int tid  = threadIdx.x;
    const int lane = tid & 31;
    const int wrp  = tid >> 5;
    const int blk0 = blockIdx.x * SC_CHUNK;
    if (blk0 >= E) return;
    const int n = min(SC_CHUNK, E - blk0);

    if (tid < N_WEIGHTS) cnt[tid] = 0;
    __syncthreads();

    const int e0 = blk0 + tid * SC_ITER;
    const bool act = (e0 < E);   // E % 4 == 0 -> all-in or all-out

    int eu[SC_ITER], ev[SC_ITER], ew[SC_ITER], er[SC_ITER];
    if (act) {
        int4 ua = *(const int4*)(u + e0);
        int4 va = *(const int4*)(v + e0);
        int4 wa = *(const int4*)(widx + e0);
        eu[0]=ua.x; eu[1]=ua.y; eu[2]=ua.z; eu[3]=ua.w;
        ev[0]=va.x; ev[1]=va.y; ev[2]=va.z; ev[3]=va.w;
        ew[0]=wa.x; ew[1]=wa.y; ew[2]=wa.z; ew[3]=wa.w;
#pragma unroll
        for (int i = 0; i < SC_ITER; i++)
            er[i] = atomicAdd(&cnt[ew[i]], 1);
    }
    __syncthreads();

    // exclusive scan of cnt[256] by warps 0-7 (tid < 256); barriers at top level
    int c = 0, s = 0;
    if (tid < N_WEIGHTS) {
        c = cnt[tid];
        s = c;
#pragma unroll
        for (int off = 1; off < 32; off <<= 1) {
            int t = __shfl_up_sync(0xffffffffu, s, off);
            if (lane >= off) s += t;
        }
        if (lane == 31) wsum[wrp] = s;
    }
    __syncthreads();
    if (wrp == 0 && lane < 8) {
        int t = wsum[lane];
#pragma unroll
        for (int off = 1; off < 8; off <<= 1) {
            int q = __shfl_up_sync(0xffu, t, off);
            if (lane >= off) t += q;
        }
        wsum[lane] = t;
    }
    __syncthreads();
    if (tid < N_WEIGHTS) {
        int incl = s + (wrp ? wsum[wrp - 1] : 0);
        lstart[tid] = incl - c;
        gbase[tid]  = tid * BIN_CAP + (c ? atomicAdd(&g_bin_fill[tid], c) : 0);
    }
    __syncthreads();

    if (act) {
#pragma unroll
        for (int i = 0; i < SC_ITER; i++) {
            int b = ew[i];
            int slot = lstart[b] + er[i];
            sval[slot] = make_int2(eu[i], ev[i]);
            sbin[slot] = (unsigned char)b;
        }
    }
    __syncthreads();

    for (int sIdx = tid; sIdx < n; sIdx += SC_THREADS) {
        int b = sbin[sIdx];
        g_suv[gbase[b] + (sIdx - lstart[b])] = sval[sIdx];
    }
}

// Warp-autonomous edge kernel: 32 edges per warp-iteration (4 groups),
// uv prefetched one iteration ahead.
__global__ void __launch_bounds__(256)
edge_mm_k(const float* __restrict__ x, const float* __restrict__ W,
          float* __restrict__ out) {
    const int w  = blockIdx.x;
    const int bs = w * BIN_CAP;
    const int be = bs + g_bin_fill[w];

    const int tid   = threadIdx.x;
    const int lane  = tid & 31;
    const int wid   = tid >> 5;
    const int qrt   = lane & 3;
    const int el    = lane >> 2;
    const int obase = qrt * 4;

    // W rows [obase, obase+4) via float4 loads, packed as f32x2 row pairs
    const float4* Wp = (const float4*)(W + (size_t)w * (D * D));
    unsigned long long wp0[D], wp1[D];
    {
        float4 r0[4], r1[4], r2[4], r3[4];
#pragma unroll
        for (int qq = 0; qq < 4; qq++) {
            r0[qq] = Wp[(obase + 0) * 4 + qq];
            r1[qq] = Wp[(obase + 1) * 4 + qq];
            r2[qq] = Wp[(obase + 2) * 4 + qq];
            r3[qq] = Wp[(obase + 3) * 4 + qq];
        }
#pragma unroll
        for (int qq = 0; qq < 4; qq++) {
            wp0[qq * 4 + 0] = pack2(r0[qq].x, r1[qq].x);
            wp0[qq * 4 + 1] = pack2(r0[qq].y, r1[qq].y);
            wp0[qq * 4 + 2] = pack2(r0[qq].z, r1[qq].z);
            wp0[qq * 4 + 3] = pack2(r0[qq].w, r1[qq].w);
            wp1[qq * 4 + 0] = pack2(r2[qq].x, r3[qq].x);
            wp1[qq * 4 + 1] = pack2(r2[qq].y, r3[qq].y);
            wp1[qq * 4 + 2] = pack2(r2[qq].z, r3[qq].z);
            wp1[qq * 4 + 3] = pack2(r2[qq].w, r3[qq].w);
        }
    }

    __shared__ float4 xs[8][32 * 5];

    const float4* x4 = (const float4*)x;
    const int gw   = blockIdx.y * 8 + wid;
    const int step = gridDim.y * 8 * 32;

    int e0 = bs + gw * 32;
    if (e0 >= be) return;

    int2 uv0[4], uv1[4];
#pragma unroll
    for (int g = 0; g < 4; g++) {
        int e = e0 + g * 8 + el;
        uv0[g] = (e < be) ? g_suv[e] : make_int2(0, 0);
        int en = e + step;
        uv1[g] = (en < be) ? g_suv[en] : make_int2(0, 0);
    }

    for (; e0 < be; e0 += step) {
        float4 xq[4];
#pragma unroll
        for (int g = 0; g < 4; g++)
            xq[g] = x4[(size_t)uv0[g].x * 4 + qrt];

        int2 uv2[4];
        const int e2 = e0 + 2 * step;
#pragma unroll
        for (int g = 0; g < 4; g++) {
            int e = e2 + g * 8 + el;
            uv2[g] = (e < be) ? g_suv[e] : make_int2(0, 0);
        }

#pragma unroll
        for (int g = 0; g < 4; g++)
            xs[wid][(g * 8 + el) * 5 + qrt] = xq[g];
        __syncwarp();

        unsigned long long a0[4] = {0ull, 0ull, 0ull, 0ull};
        unsigned long long a1[4] = {0ull, 0ull, 0ull, 0ull};
#pragma unroll
        for (int q = 0; q < 4; q++) {
#pragma unroll
            for (int g = 0; g < 4; g++) {
                float4 xv = xs[wid][(g * 8 + el) * 5 + q];
                unsigned long long b0 = pack2(xv.x, xv.x);
                unsigned long long b1 = pack2(xv.y, xv.y);
                unsigned long long b2 = pack2(xv.z, xv.z);
                unsigned long long b3 = pack2(xv.w, xv.w);
                fma2(a0[g], wp0[q * 4 + 0], b0);  fma2(a1[g], wp1[q * 4 + 0], b0);
                fma2(a0[g], wp0[q * 4 + 1], b1);  fma2(a1[g], wp1[q * 4 + 1], b1);
                fma2(a0[g], wp0[q * 4 + 2], b2);  fma2(a1[g], wp1[q * 4 + 2], b2);
                fma2(a0[g], wp0[q * 4 + 3], b3);  fma2(a1[g], wp1[q * 4 + 3], b3);
            }
        }

#pragma unroll
        for (int g = 0; g < 4; g++) {
            if (e0 + g * 8 + el < be) {
                float r0, r1, r2, r3;
                unpack2(a0[g], r0, r1);
                unpack2(a1[g], r2, r3);
                red_add_v4(out + (size_t)uv0[g].y * D + obase, r0, r1, r2, r3);
            }
        }
        __syncwarp();

#pragma unroll
        for (int g = 0; g < 4; g++) {
            uv0[g] = uv1[g];
            uv1[g] = uv2[g];
        }
    }
}

// relu: read accumulator -> write output; re-zero accumulator and bin counts.
__global__ void __launch_bounds__(256)
relu_k(float* __restrict__ out, int n4) {
    int i = blockIdx.x * blockDim.x + threadIdx.x;
    if (i < n4) {
        float4* a4 = (float4*)g_acc;
        float4 v = a4[i];
        v.x = fmaxf(v.x, 0.f);
        v.y = fmaxf(v.y, 0.f);
        v.z = fmaxf(v.z, 0.f);
        v.w = fmaxf(v.w, 0.f);
        ((float4*)out)[i] = v;
        a4[i] = make_float4(0.f, 0.f, 0.f, 0.f);
    }
    if (blockIdx.x == 0 && threadIdx.x < N_WEIGHTS)
        g_bin_fill[threadIdx.x] = 0;
}

// ---------------- launcher ----------------
extern "C" void kernel_launch(void* const* d_in, const int* in_sizes, int n_in,
                              void* d_out, int out_size) {
    const float* x    = (const float*)d_in[0];
    const float* W    = (const float*)d_in[1];
    const int*   u    = (const int*)d_in[2];
    const int*   v    = (const int*)d_in[3];
    const int*   widx = (const int*)d_in[4];
    float* out = (float*)d_out;

    const int E = in_sizes[2];

    float* acc;
    cudaGetSymbolAddress((void**)&acc, g_acc);

    scatter_k<<<(E + SC_CHUNK - 1) / SC_CHUNK, SC_THREADS>>>(u, v, widx, E);
    edge_mm_k<<<dim3(N_WEIGHTS, MM_GRID_Y), 256>>>(x, W, acc);
    int n4 = out_size / 4;
    relu_k<<<(n4 + 255) / 256, 256>>>(out, n4);
}

// round 14
// speedup vs baseline: 3.4103x; 1.0032x over previous
#include <cuda_runtime.h>
#include <cuda_bf16.h>
#include <cstdint>

#define N_NODES   100000
#define N_EDGES   1600000
#define N_WEIGHTS 256
#define D         16
#define SC_THREADS 512
#define SC_ITER   4
#define SC_CHUNK  (SC_THREADS * SC_ITER)   // 2048 edges per scatter block
#define MM_GRID_Y 4
#define BIN_CAP   8192

// ---------------- scratch (persistent across graph replays) ----------------
__device__ int   g_bin_fill[N_WEIGHTS];   // per-bin COUNT; zero at load, re-zeroed by relu_k
__device__ int2  g_suv[N_WEIGHTS * BIN_CAP];
__device__ float g_acc[N_NODES * D];      // zero at load, re-zeroed by relu_k

// ---------------- helpers ----------------
__device__ __forceinline__ unsigned long long pack2(float lo, float hi) {
    unsigned long long r;
    asm("mov.b64 %0, {%1, %2};" : "=l"(r) : "f"(lo), "f"(hi));
    return r;
}
__device__ __forceinline__ void fma2(unsigned long long& d,
                                     unsigned long long a, unsigned long long b) {
    asm("fma.rn.f32x2 %0, %1, %2, %0;" : "+l"(d) : "l"(a), "l"(b));
}
__device__ __forceinline__ void unpack2(unsigned long long v, float& lo, float& hi) {
    asm("mov.b64 {%0, %1}, %2;" : "=f"(lo), "=f"(hi) : "l"(v));
}
__device__ __forceinline__ void red_add_v4(float* p, float a, float b, float c, float d) {
    asm volatile("red.global.add.v4.f32 [%0], {%1, %2, %3, %4};"
                 :: "l"(p), "f"(a), "f"(b), "f"(c), "f"(d) : "memory");
}

// ---------------- kernels ----------------

// One-pass counting-sort scatter into bump-allocated bin regions.
__global__ void __launch_bounds__(SC_THREADS)
scatter_k(const int* __restrict__ u, const int* __restrict__ v,
          const int* __restrict__ widx, int E) {
    __shared__ int  cnt[N_WEIGHTS];
    __shared__ int  lstart[N_WEIGHTS];
    __shared__ int  gbase[N_WEIGHTS];
    __shared__ int  wsum[8];
    __shared__ int2 sval[SC_CHUNK];
    __shared__ unsigned char sbin[SC_CHUNK];

    const int tid  = threadIdx.x;
    const int lane = tid & 31;
    const int wrp  = tid >> 5;
    const int blk0 = blockIdx.x * SC_CHUNK;
    if (blk0 >= E) return;
    const int n = min(SC_CHUNK, E - blk0);

    if (tid < N_WEIGHTS) cnt[tid] = 0;
    __syncthreads();

    const int e0 = blk0 + tid * SC_ITER;
    const bool act = (e0 < E);

    int eu[SC_ITER], ev[SC_ITER], ew[SC_ITER], er[SC_ITER];
    if (act) {
        int4 ua = *(const int4*)(u + e0);
        int4 va = *(const int4*)(v + e0);
        int4 wa = *(const int4*)(widx + e0);
        eu[0]=ua.x; eu[1]=ua.y; eu[2]=ua.z; eu[3]=ua.w;
        ev[0]=va.x; ev[1]=va.y; ev[2]=va.z; ev[3]=va.w;
        ew[0]=wa.x; ew[1]=wa.y; ew[2]=wa.z; ew[3]=wa.w;
#pragma unroll
        for (int i = 0; i < SC_ITER; i++)
            er[i] = atomicAdd(&cnt[ew[i]], 1);
    }
    __syncthreads();

    int c = 0, s = 0;
    if (tid < N_WEIGHTS) {
        c = cnt[tid];
        s = c;
#pragma unroll
        for (int off = 1; off < 32; off <<= 1) {
            int t = __shfl_up_sync(0xffffffffu, s, off);
            if (lane >= off) s += t;
        }
        if (lane == 31) wsum[wrp] = s;
    }
    __syncthreads();
    if (wrp == 0 && lane < 8) {
        int t = wsum[lane];
#pragma unroll
        for (int off = 1; off < 8; off <<= 1) {
            int q = __shfl_up_sync(0xffu, t, off);
            if (lane >= off) t += q;
        }
        wsum[lane] = t;
    }
    __syncthreads();
    if (tid < N_WEIGHTS) {
        int incl = s + (wrp ? wsum[wrp - 1] : 0);
        lstart[tid] = incl - c;
        gbase[tid]  = tid * BIN_CAP + (c ? atomicAdd(&g_bin_fill[tid], c) : 0);
    }
    __syncthreads();

    if (act) {
#pragma unroll
        for (int i = 0; i < SC_ITER; i++) {
            int b = ew[i];
            int slot = lstart[b] + er[i];
            sval[slot] = make_int2(eu[i], ev[i]);
            sbin[slot] = (unsigned char)b;
        }
    }
    __syncthreads();

    for (int sIdx = tid; sIdx < n; sIdx += SC_THREADS) {
        int b = sbin[sIdx];
        g_suv[gbase[b] + (sIdx - lstart[b])] = sval[sIdx];
    }
}

// Warp-autonomous edge kernel: 32 edges/warp-iter, x pipelined one iteration
// ahead through a double-buffered warp-private smem slab.
__global__ void __launch_bounds__(256)
edge_mm_k(const float* __restrict__ x, const float* __restrict__ W,
          float* __restrict__ out) {
    const int w  = blockIdx.x;
    const int bs = w * BIN_CAP;
    const int be = bs + g_bin_fill[w];

    const int tid   = threadIdx.x;
    const int lane  = tid & 31;
    const int wid   = tid >> 5;
    const int qrt   = lane & 3;
    const int el    = lane >> 2;
    const int obase = qrt * 4;

    // W rows [obase, obase+4) via float4 loads, packed as f32x2 row pairs
    const float4* Wp = (const float4*)(W + (size_t)w * (D * D));
    unsigned long long wp0[D], wp1[D];
    {
        float4 r0[4], r1[4], r2[4], r3[4];
#pragma unroll
        for (int qq = 0; qq < 4; qq++) {
            r0[qq] = Wp[(obase + 0) * 4 + qq];
            r1[qq] = Wp[(obase + 1) * 4 + qq];
            r2[qq] = Wp[(obase + 2) * 4 + qq];
            r3[qq] = Wp[(obase + 3) * 4 + qq];
        }
#pragma unroll
        for (int qq = 0; qq < 4; qq++) {
            wp0[qq * 4 + 0] = pack2(r0[qq].x, r1[qq].x);
            wp0[qq * 4 + 1] = pack2(r0[qq].y, r1[qq].y);
            wp0[qq * 4 + 2] = pack2(r0[qq].z, r1[qq].z);
            wp0[qq * 4 + 3] = pack2(r0[qq].w, r1[qq].w);
            wp1[qq * 4 + 0] = pack2(r2[qq].x, r3[qq].x);
            wp1[qq * 4 + 1] = pack2(r2[qq].y, r3[qq].y);
            wp1[qq * 4 + 2] = pack2(r2[qq].z, r3[qq].z);
            wp1[qq * 4 + 3] = pack2(r2[qq].w, r3[qq].w);
        }
    }

    // double-buffered: 8 warps x 2 bufs x 32 edges x 5-float4 = 40KB
    __shared__ float4 xs[8][2][32 * 5];

    const float4* x4 = (const float4*)x;
    const int gw   = blockIdx.y * 8 + wid;
    const int step = gridDim.y * 8 * 32;

    int e0 = bs + gw * 32;
    if (e0 >= be) return;

    int2 uv0[4], uv1[4];
#pragma unroll
    for (int g = 0; g < 4; g++) {
        int e = e0 + g * 8 + el;
        uv0[g] = (e < be) ? g_suv[e] : make_int2(0, 0);
        int en = e + step;
        uv1[g] = (en < be) ? g_suv[en] : make_int2(0, 0);
    }

    // prologue: stage iter-0 x into buf 0
#pragma unroll
    for (int g = 0; g < 4; g++)
        xs[wid][0][(g * 8 + el) * 5 + qrt] = x4[(size_t)uv0[g].x * 4 + qrt];
    __syncwarp();

    int buf = 0;
    for (; e0 < be; e0 += step) {
        // issue next iteration's x loads + uv(i+2) loads EARLY (hide under compute)
        float4 xn[4];
#pragma unroll
        for (int g = 0; g < 4; g++)
            xn[g] = x4[(size_t)uv1[g].x * 4 + qrt];

        int2 uv2[4];
        const int e2 = e0 + 2 * step;
#pragma unroll
        for (int g = 0; g < 4; g++) {
            int e = e2 + g * 8 + el;
            uv2[g] = (e < be) ? g_suv[e] : make_int2(0, 0);
        }

        // compute from current buffer
        unsigned long long a0[4] = {0ull, 0ull, 0ull, 0ull};
        unsigned long long a1[4] = {0ull, 0ull, 0ull, 0ull};
#pragma unroll
        for (int q = 0; q < 4; q++) {
#pragma unroll
            for (int g = 0; g < 4; g++) {
                float4 xv = xs[wid][buf][(g * 8 + el) * 5 + q];
                unsigned long long b0 = pack2(xv.x, xv.x);
                unsigned long long b1 = pack2(xv.y, xv.y);
                unsigned long long b2 = pack2(xv.z, xv.z);
                unsigned long long b3 = pack2(xv.w, xv.w);
                fma2(a0[g], wp0[q * 4 + 0], b0);  fma2(a1[g], wp1[q * 4 + 0], b0);
                fma2(a0[g], wp0[q * 4 + 1], b1);  fma2(a1[g], wp1[q * 4 + 1], b1);
                fma2(a0[g], wp0[q * 4 + 2], b2);  fma2(a1[g], wp1[q * 4 + 2], b2);
                fma2(a0[g], wp0[q * 4 + 3], b3);  fma2(a1[g], wp1[q * 4 + 3], b3);
            }
        }

#pragma unroll
        for (int g = 0; g < 4; g++) {
            if (e0 + g * 8 + el < be) {
                float r0, r1, r2, r3;
                unpack2(a0[g], r0, r1);
                unpack2(a1[g], r2, r3);
                red_add_v4(out + (size_t)uv0[g].y * D + obase, r0, r1, r2, r3);
            }
        }

        // stage next iteration's x into the other buffer
#pragma unroll
        for (int g = 0; g < 4; g++)
            xs[wid][buf ^ 1][(g * 8 + el) * 5 + qrt] = xn[g];
        __syncwarp();
        buf ^= 1;

#pragma unroll
        for (int g = 0; g < 4; g++) {
            uv0[g] = uv1[g];
            uv1[g] = uv2[g];
        }
    }
}

// relu: read accumulator -> write output; re-zero accumulator and bin counts.
__global__ void __launch_bounds__(256)
relu_k(float* __restrict__ out, int n4) {
    int i = blockIdx.x * blockDim.x + threadIdx.x;
    if (i < n4) {
        float4* a4 = (float4*)g_acc;
        float4 v = a4[i];
        v.x = fmaxf(v.x, 0.f);
        v.y = fmaxf(v.y, 0.f);
        v.z = fmaxf(v.z, 0.f);
        v.w = fmaxf(v.w, 0.f);
        ((float4*)out)[i] = v;
        a4[i] = make_float4(0.f, 0.f, 0.f, 0.f);
    }
    if (blockIdx.x == 0 && threadIdx.x < N_WEIGHTS)
        g_bin_fill[threadIdx.x] = 0;
}

// ---------------- launcher ----------------
extern "C" void kernel_launch(void* const* d_in, const int* in_sizes, int n_in,
                              void* d_out, int out_size) {
    const float* x    = (const float*)d_in[0];
    const float* W    = (const float*)d_in[1];
    const int*   u    = (const int*)d_in[2];
    const int*   v    = (const int*)d_in[3];
    const int*   widx = (const int*)d_in[4];
    float* out = (float*)d_out;

    const int E = in_sizes[2];

    float* acc;
    cudaGetSymbolAddress((void**)&acc, g_acc);

    scatter_k<<<(E + SC_CHUNK - 1) / SC_CHUNK, SC_THREADS>>>(u, v, widx, E);
    edge_mm_k<<<dim3(N_WEIGHTS, MM_GRID_Y), 256>>>(x, W, acc);
    int n4 = out_size / 4;
    relu_k<<<(n4 + 255) / 256, 256>>>(out, n4);
}

// round 15
// speedup vs baseline: 3.4470x; 1.0108x over previous
#include <cuda_runtime.h>
#include <cuda_bf16.h>
#include <cstdint>

#define N_NODES   100000
#define N_EDGES   1600000
#define N_WEIGHTS 256
#define D         16
#define SC_THREADS 512
#define SC_ITER   4
#define SC_CHUNK  (SC_THREADS * SC_ITER)   // 2048 edges per scatter block
#define MM_GRID_Y 4
#define BIN_CAP   8192
#define ACC_N4    (N_NODES * D / 4)        // 400,000 float4s

// ---------------- scratch (persistent across graph replays) ----------------
__device__ int   g_bin_fill[N_WEIGHTS];   // per-bin COUNT; zero at load, re-zeroed by relu_k
__device__ int2  g_suv[N_WEIGHTS * BIN_CAP];
__device__ float g_acc[N_NODES * D];      // zeroed by scatter_k each call

// ---------------- helpers ----------------
__device__ __forceinline__ unsigned long long pack2(float lo, float hi) {
    unsigned long long r;
    asm("mov.b64 %0, {%1, %2};" : "=l"(r) : "f"(lo), "f"(hi));
    return r;
}
__device__ __forceinline__ void fma2(unsigned long long& d,
                                     unsigned long long a, unsigned long long b) {
    asm("fma.rn.f32x2 %0, %1, %2, %0;" : "+l"(d) : "l"(a), "l"(b));
}
__device__ __forceinline__ void unpack2(unsigned long long v, float& lo, float& hi) {
    asm("mov.b64 {%0, %1}, %2;" : "=f"(lo), "=f"(hi) : "l"(v));
}
__device__ __forceinline__ void red_add_v4(float* p, float a, float b, float c, float d) {
    asm volatile("red.global.add.v4.f32 [%0], {%1, %2, %3, %4};"
                 :: "l"(p), "f"(a), "f"(b), "f"(c), "f"(d) : "memory");
}

// ---------------- kernels ----------------

// One-pass counting-sort scatter into bump-allocated bin regions.
// Also zeroes g_acc for this call (stores ride in scatter's stall shadow).
__global__ void __launch_bounds__(SC_THREADS)
scatter_k(const int* __restrict__ u, const int* __restrict__ v,
          const int* __restrict__ widx, int E) {
    __shared__ int  cnt[N_WEIGHTS];
    __shared__ int  lstart[N_WEIGHTS];
    __shared__ int  gbase[N_WEIGHTS];
    __shared__ int  wsum[8];
    __shared__ int2 sval[SC_CHUNK];
    __shared__ unsigned char sbin[SC_CHUNK];

    const int tid  = threadIdx.x;
    const int lane = tid & 31;
    const int wrp  = tid >> 5;
    const int blk0 = blockIdx.x * SC_CHUNK;
    if (blk0 >= E) return;
    const int n = min(SC_CHUNK, E - blk0);

    // zero accumulator slice (coalesced, overlaps with latency-bound phases)
    {
        int z = blockIdx.x * SC_THREADS + tid;
        if (z < ACC_N4)
            ((float4*)g_acc)[z] = make_float4(0.f, 0.f, 0.f, 0.f);
    }

    if (tid < N_WEIGHTS) cnt[tid] = 0;
    __syncthreads();

    const int e0 = blk0 + tid * SC_ITER;
    const bool act = (e0 < E);

    int eu[SC_ITER], ev[SC_ITER], ew[SC_ITER], er[SC_ITER];
    if (act) {
        int4 ua = *(const int4*)(u + e0);
        int4 va = *(const int4*)(v + e0);
        int4 wa = *(const int4*)(widx + e0);
        eu[0]=ua.x; eu[1]=ua.y; eu[2]=ua.z; eu[3]=ua.w;
        ev[0]=va.x; ev[1]=va.y; ev[2]=va.z; ev[3]=va.w;
        ew[0]=wa.x; ew[1]=wa.y; ew[2]=wa.z; ew[3]=wa.w;
#pragma unroll
        for (int i = 0; i < SC_ITER; i++)
            er[i] = atomicAdd(&cnt[ew[i]], 1);
    }
    __syncthreads();

    int c = 0, s = 0;
    if (tid < N_WEIGHTS) {
        c = cnt[tid];
        s = c;
#pragma unroll
        for (int off = 1; off < 32; off <<= 1) {
            int t = __shfl_up_sync(0xffffffffu, s, off);
            if (lane >= off) s += t;
        }
        if (lane == 31) wsum[wrp] = s;
    }
    __syncthreads();
    if (wrp == 0 && lane < 8) {
        int t = wsum[lane];
#pragma unroll
        for (int off = 1; off < 8; off <<= 1) {
            int q = __shfl_up_sync(0xffu, t, off);
            if (lane >= off) t += q;
        }
        wsum[lane] = t;
    }
    __syncthreads();
    if (tid < N_WEIGHTS) {
        int incl = s + (wrp ? wsum[wrp - 1] : 0);
        lstart[tid] = incl - c;
        gbase[tid]  = tid * BIN_CAP + (c ? atomicAdd(&g_bin_fill[tid], c) : 0);
    }
    __syncthreads();

    if (act) {
#pragma unroll
        for (int i = 0; i < SC_ITER; i++) {
            int b = ew[i];
            int slot = lstart[b] + er[i];
            sval[slot] = make_int2(eu[i], ev[i]);
            sbin[slot] = (unsigned char)b;
        }
    }
    __syncthreads();

    for (int sIdx = tid; sIdx < n; sIdx += SC_THREADS) {
        int b = sbin[sIdx];
        g_suv[gbase[b] + (sIdx - lstart[b])] = sval[sIdx];
    }
}

// Warp-autonomous edge kernel: 32 edges/warp-iter, x pipelined one iteration
// ahead through a double-buffered warp-private smem slab.
__global__ void __launch_bounds__(256)
edge_mm_k(const float* __restrict__ x, const float* __restrict__ W,
          float* __restrict__ out) {
    const int w  = blockIdx.x;
    const int bs = w * BIN_CAP;
    const int be = bs + g_bin_fill[w];

    const int tid   = threadIdx.x;
    const int lane  = tid & 31;
    const int wid   = tid >> 5;
    const int qrt   = lane & 3;
    const int el    = lane >> 2;
    const int obase = qrt * 4;

    const float4* Wp = (const float4*)(W + (size_t)w * (D * D));
    unsigned long long wp0[D], wp1[D];
    {
        float4 r0[4], r1[4], r2[4], r3[4];
#pragma unroll
        for (int qq = 0; qq < 4; qq++) {
            r0[qq] = Wp[(obase + 0) * 4 + qq];
            r1[qq] = Wp[(obase + 1) * 4 + qq];
            r2[qq] = Wp[(obase + 2) * 4 + qq];
            r3[qq] = Wp[(obase + 3) * 4 + qq];
        }
#pragma unroll
        for (int qq = 0; qq < 4; qq++) {
            wp0[qq * 4 + 0] = pack2(r0[qq].x, r1[qq].x);
            wp0[qq * 4 + 1] = pack2(r0[qq].y, r1[qq].y);
            wp0[qq * 4 + 2] = pack2(r0[qq].z, r1[qq].z);
            wp0[qq * 4 + 3] = pack2(r0[qq].w, r1[qq].w);
            wp1[qq * 4 + 0] = pack2(r2[qq].x, r3[qq].x);
            wp1[qq * 4 + 1] = pack2(r2[qq].y, r3[qq].y);
            wp1[qq * 4 + 2] = pack2(r2[qq].z, r3[qq].z);
            wp1[qq * 4 + 3] = pack2(r2[qq].w, r3[qq].w);
        }
    }

    __shared__ float4 xs[8][2][32 * 5];

    const float4* x4 = (const float4*)x;
    const int gw   = blockIdx.y * 8 + wid;
    const int step = gridDim.y * 8 * 32;

    int e0 = bs + gw * 32;
    if (e0 >= be) return;

    int2 uv0[4], uv1[4];
#pragma unroll
    for (int g = 0; g < 4; g++) {
        int e = e0 + g * 8 + el;
        uv0[g] = (e < be) ? g_suv[e] : make_int2(0, 0);
        int en = e + step;
        uv1[g] = (en < be) ? g_suv[en] : make_int2(0, 0);
    }

#pragma unroll
    for (int g = 0; g < 4; g++)
        xs[wid][0][(g * 8 + el) * 5 + qrt] = x4[(size_t)uv0[g].x * 4 + qrt];
    __syncwarp();

    int buf = 0;
    for (; e0 < be; e0 += step) {
        float4 xn[4];
#pragma unroll
        for (int g = 0; g < 4; g++)
            xn[g] = x4[(size_t)uv1[g].x * 4 + qrt];

        int2 uv2[4];
        const int e2 = e0 + 2 * step;
#pragma unroll
        for (int g = 0; g < 4; g++) {
            int e = e2 + g * 8 + el;
            uv2[g] = (e < be) ? g_suv[e] : make_int2(0, 0);
        }

        unsigned long long a0[4] = {0ull, 0ull, 0ull, 0ull};
        unsigned long long a1[4] = {0ull, 0ull, 0ull, 0ull};
#pragma unroll
        for (int q = 0; q < 4; q++) {
#pragma unroll
            for (int g = 0; g < 4; g++) {
                float4 xv = xs[wid][buf][(g * 8 + el) * 5 + q];
                unsigned long long b0 = pack2(xv.x, xv.x);
                unsigned long long b1 = pack2(xv.y, xv.y);
                unsigned long long b2 = pack2(xv.z, xv.z);
                unsigned long long b3 = pack2(xv.w, xv.w);
                fma2(a0[g], wp0[q * 4 + 0], b0);  fma2(a1[g], wp1[q * 4 + 0], b0);
                fma2(a0[g], wp0[q * 4 + 1], b1);  fma2(a1[g], wp1[q * 4 + 1], b1);
                fma2(a0[g], wp0[q * 4 + 2], b2);  fma2(a1[g], wp1[q * 4 + 2], b2);
                fma2(a0[g], wp0[q * 4 + 3], b3);  fma2(a1[g], wp1[q * 4 + 3], b3);
            }
        }

#pragma unroll
        for (int g = 0; g < 4; g++) {
            if (e0 + g * 8 + el < be) {
                float r0, r1, r2, r3;
                unpack2(a0[g], r0, r1);
                unpack2(a1[g], r2, r3);
                red_add_v4(out + (size_t)uv0[g].y * D + obase, r0, r1, r2, r3);
            }
        }

#pragma unroll
        for (int g = 0; g < 4; g++)
            xs[wid][buf ^ 1][(g * 8 + el) * 5 + qrt] = xn[g];
        __syncwarp();
        buf ^= 1;

#pragma unroll
        for (int g = 0; g < 4; g++) {
            uv0[g] = uv1[g];
            uv1[g] = uv2[g];
        }
    }
}

// relu: read accumulator -> write output (no rezero; scatter_k zeroes g_acc).
// Re-zeroes only the bin counters for the next replay.
__global__ void __launch_bounds__(256)
relu_k(float* __restrict__ out, int n4) {
    const float4* a4 = (const float4*)g_acc;
    float4* o4 = (float4*)out;
    int i = blockIdx.x * 512 + threadIdx.x;
#pragma unroll
    for (int rep = 0; rep < 2; rep++, i += 256) {
        if (i < n4) {
            float4 v = a4[i];
            v.x = fmaxf(v.x, 0.f);
            v.y = fmaxf(v.y, 0.f);
            v.z = fmaxf(v.z, 0.f);
            v.w = fmaxf(v.w, 0.f);
            o4[i] = v;
        }
    }
    if (blockIdx.x == 0 && threadIdx.x < N_WEIGHTS)
        g_bin_fill[threadIdx.x] = 0;
}

// ---------------- launcher ----------------
extern "C" void kernel_launch(void* const* d_in, const int* in_sizes, int n_in,
                              void* d_out, int out_size) {
    const float* x    = (const float*)d_in[0];
    const float* W    = (const float*)d_in[1];
    const int*   u    = (const int*)d_in[2];
    const int*   v    = (const int*)d_in[3];
    const int*   widx = (const int*)d_in[4];
    float* out = (float*)d_out;

    const int E = in_sizes[2];

    float* acc;
    cudaGetSymbolAddress((void**)&acc, g_acc);

    scatter_k<<<(E + SC_CHUNK - 1) / SC_CHUNK, SC_THREADS>>>(u, v, widx, E);
    edge_mm_k<<<dim3(N_WEIGHTS, MM_GRID_Y), 256>>>(x, W, acc);
    int n4 = out_size / 4;
    relu_k<<<(n4 + 511) / 512, 256>>>(out, n4);
}

// round 16
// speedup vs baseline: 3.6764x; 1.0666x over previous
#include <cuda_runtime.h>
#include <cuda_bf16.h>
#include <cstdint>

#define N_NODES   100000
#define N_EDGES   1600000
#define N_WEIGHTS 256
#define D         16
#define SC_THREADS 512
#define SC_ITER   8
#define SC_CHUNK  (SC_THREADS * SC_ITER)   // 4096 edges per scatter block
#define MM_GRID_Y 2                         // grid = (512 segments, 2)
#define BIN_CAP   8192
#define SEG_CAP   (BIN_CAP / 2)             // 4096 slots per half-segment
#define ACC_N4    (N_NODES * D / 4)         // 400,000 float4s

// ---------------- scratch (persistent across graph replays) ----------------
__device__ int   g_bin_fill[2 * N_WEIGHTS]; // [parity][bin] counts; zeroed by relu_k
__device__ int2  g_suv[N_WEIGHTS * BIN_CAP];
__device__ float g_acc[N_NODES * D];        // zeroed by scatter_k each call

// ---------------- helpers ----------------
__device__ __forceinline__ unsigned long long pack2(float lo, float hi) {
    unsigned long long r;
    asm("mov.b64 %0, {%1, %2};" : "=l"(r) : "f"(lo), "f"(hi));
    return r;
}
__device__ __forceinline__ void fma2(unsigned long long& d,
                                     unsigned long long a, unsigned long long b) {
    asm("fma.rn.f32x2 %0, %1, %2, %0;" : "+l"(d) : "l"(a), "l"(b));
}
__device__ __forceinline__ void unpack2(unsigned long long v, float& lo, float& hi) {
    asm("mov.b64 {%0, %1}, %2;" : "=f"(lo), "=f"(hi) : "l"(v));
}
__device__ __forceinline__ void red_add_v4(float* p, float a, float b, float c, float d) {
    asm volatile("red.global.add.v4.f32 [%0], {%1, %2, %3, %4};"
                 :: "l"(p), "f"(a), "f"(b), "f"(c), "f"(d) : "memory");
}

// ---------------- kernels ----------------

// One-pass counting-sort scatter into bump-allocated HALF-BIN segments.
// Block parity selects which of the bin's two counters/regions to fill,
// halving per-address global-atomic serialization. Also zeroes g_acc.
__global__ void __launch_bounds__(SC_THREADS)
scatter_k(const int* __restrict__ u, const int* __restrict__ v,
          const int* __restrict__ widx, int E) {
    __shared__ int  cnt[N_WEIGHTS];
    __shared__ int  lstart[N_WEIGHTS];
    __shared__ int  gbase[N_WEIGHTS];
    __shared__ int  wsum[8];
    __shared__ int2 sval[SC_CHUNK];
    __shared__ unsigned char sbin2[SC_CHUNK];

    const int tid  = threadIdx.x;
    const int lane = tid & 31;
    const int wrp  = tid >> 5;
    const int par  = blockIdx.x & 1;
    const int blk0 = blockIdx.x * SC_CHUNK;
    if (blk0 >= E) return;
    const int n = min(SC_CHUNK, E - blk0);

    // zero accumulator slice (2 float4 per thread; rides in stall shadow)
    {
        int z = blockIdx.x * (2 * SC_THREADS) + tid;
        if (z < ACC_N4) ((float4*)g_acc)[z] = make_float4(0.f, 0.f, 0.f, 0.f);
        z += SC_THREADS;
        if (z < ACC_N4) ((float4*)g_acc)[z] = make_float4(0.f, 0.f, 0.f, 0.f);
    }

    if (tid < N_WEIGHTS) cnt[tid] = 0;
    __syncthreads();

    const int e0 = blk0 + tid * SC_ITER;
    const bool act = (e0 < E);   // E % 8 == 0

    int eu[SC_ITER], ev[SC_ITER], ew[SC_ITER], er[SC_ITER];
    if (act) {
        const int4* u4 = (const int4*)(u + e0);
        const int4* v4 = (const int4*)(v + e0);
        const int4* w4 = (const int4*)(widx + e0);
        int4 ua = u4[0], ub = u4[1];
        int4 va = v4[0], vb = v4[1];
        int4 wa = w4[0], wb = w4[1];
        eu[0]=ua.x; eu[1]=ua.y; eu[2]=ua.z; eu[3]=ua.w;
        eu[4]=ub.x; eu[5]=ub.y; eu[6]=ub.z; eu[7]=ub.w;
        ev[0]=va.x; ev[1]=va.y; ev[2]=va.z; ev[3]=va.w;
        ev[4]=vb.x; ev[5]=vb.y; ev[6]=vb.z; ev[7]=vb.w;
        ew[0]=wa.x; ew[1]=wa.y; ew[2]=wa.z; ew[3]=wa.w;
        ew[4]=wb.x; ew[5]=wb.y; ew[6]=wb.z; ew[7]=wb.w;
#pragma unroll
        for (int i = 0; i < SC_ITER; i++)
            er[i] = atomicAdd(&cnt[ew[i]], 1);
    }
    __syncthreads();

    // issue global bump-alloc EARLY (parallel with scan), then scan cnt[256]
    int c = 0, s = 0, gb = 0;
    if (tid < N_WEIGHTS) {
        c = cnt[tid];
        gb = c ? atomicAdd(&g_bin_fill[par * N_WEIGHTS + tid], c) : 0;   // hidden under scan
        s = c;
#pragma unroll
        for (int off = 1; off < 32; off <<= 1) {
            int t = __shfl_up_sync(0xffffffffu, s, off);
            if (lane >= off) s += t;
        }
        if (lane == 31) wsum[wrp] = s;
    }
    __syncthreads();
    if (wrp == 0 && lane < 8) {
        int t = wsum[lane];
#pragma unroll
        for (int off = 1; off < 8; off <<= 1) {
            int q = __shfl_up_sync(0xffu, t, off);
            if (lane >= off) t += q;
        }
        wsum[lane] = t;
    }
    __syncthreads();
    if (tid < N_WEIGHTS) {
        int incl = s + (wrp ? wsum[wrp - 1] : 0);
        lstart[tid] = incl - c;
        gbase[tid]  = tid * BIN_CAP + par * SEG_CAP + gb;
    }
    __syncthreads();

    if (act) {
#pragma unroll
        for (int i = 0; i < SC_ITER; i++) {
            int b = ew[i];
            int slot = lstart[b] + er[i];
            sval[slot]  = make_int2(eu[i], ev[i]);
            sbin2[slot] = (unsigned char)b;
        }
    }
    __syncthreads();

    for (int sIdx = tid; sIdx < n; sIdx += SC_THREADS) {
        int b = sbin2[sIdx];
        g_suv[gbase[b] + (sIdx - lstart[b])] = sval[sIdx];
    }
}

// Warp-autonomous edge kernel over 512 half-bin segments.
// 32 edges/warp-iter, x pipelined via double-buffered warp-private smem.
__global__ void __launch_bounds__(256)
edge_mm_k(const float* __restrict__ x, const float* __restrict__ W,
          float* __restrict__ out) {
    const int seg = blockIdx.x & 1;
    const int w   = blockIdx.x >> 1;
    const int bs  = w * BIN_CAP + seg * SEG_CAP;
    const int be  = bs + g_bin_fill[seg * N_WEIGHTS + w];

    const int tid   = threadIdx.x;
    const int lane  = tid & 31;
    const int wid   = tid >> 5;
    const int qrt   = lane & 3;
    const int el    = lane >> 2;
    const int obase = qrt * 4;

    const float4* Wp = (const float4*)(W + (size_t)w * (D * D));
    unsigned long long wp0[D], wp1[D];
    {
        float4 r0[4], r1[4], r2[4], r3[4];
#pragma unroll
        for (int qq = 0; qq < 4; qq++) {
            r0[qq] = Wp[(obase + 0) * 4 + qq];
            r1[qq] = Wp[(obase + 1) * 4 + qq];
            r2[qq] = Wp[(obase + 2) * 4 + qq];
            r3[qq] = Wp[(obase + 3) * 4 + qq];
        }
#pragma unroll
        for (int qq = 0; qq < 4; qq++) {
            wp0[qq * 4 + 0] = pack2(r0[qq].x, r1[qq].x);
            wp0[qq * 4 + 1] = pack2(r0[qq].y, r1[qq].y);
            wp0[qq * 4 + 2] = pack2(r0[qq].z, r1[qq].z);
            wp0[qq * 4 + 3] = pack2(r0[qq].w, r1[qq].w);
            wp1[qq * 4 + 0] = pack2(r2[qq].x, r3[qq].x);
            wp1[qq * 4 + 1] = pack2(r2[qq].y, r3[qq].y);
            wp1[qq * 4 + 2] = pack2(r2[qq].z, r3[qq].z);
            wp1[qq * 4 + 3] = pack2(r2[qq].w, r3[qq].w);
        }
    }

    __shared__ float4 xs[8][2][32 * 5];

    const float4* x4 = (const float4*)x;
    const int gw   = blockIdx.y * 8 + wid;
    const int step = gridDim.y * 8 * 32;

    int e0 = bs + gw * 32;
    if (e0 >= be) return;

    int2 uv0[4], uv1[4];
#pragma unroll
    for (int g = 0; g < 4; g++) {
        int e = e0 + g * 8 + el;
        uv0[g] = (e < be) ? g_suv[e] : make_int2(0, 0);
        int en = e + step;
        uv1[g] = (en < be) ? g_suv[en] : make_int2(0, 0);
    }

#pragma unroll
    for (int g = 0; g < 4; g++)
        xs[wid][0][(g * 8 + el) * 5 + qrt] = x4[(size_t)uv0[g].x * 4 + qrt];
    __syncwarp();

    int buf = 0;
    for (; e0 < be; e0 += step) {
        float4 xn[4];
#pragma unroll
        for (int g = 0; g < 4; g++)
            xn[g] = x4[(size_t)uv1[g].x * 4 + qrt];

        int2 uv2[4];
        const int e2 = e0 + 2 * step;
#pragma unroll
        for (int g = 0; g < 4; g++) {
            int e = e2 + g * 8 + el;
            uv2[g] = (e < be) ? g_suv[e] : make_int2(0, 0);
        }

        unsigned long long a0[4] = {0ull, 0ull, 0ull, 0ull};
        unsigned long long a1[4] = {0ull, 0ull, 0ull, 0ull};
#pragma unroll
        for (int q = 0; q < 4; q++) {
#pragma unroll
            for (int g = 0; g < 4; g++) {
                float4 xv = xs[wid][buf][(g * 8 + el) * 5 + q];
                unsigned long long b0 = pack2(xv.x, xv.x);
                unsigned long long b1 = pack2(xv.y, xv.y);
                unsigned long long b2 = pack2(xv.z, xv.z);
                unsigned long long b3 = pack2(xv.w, xv.w);
                fma2(a0[g], wp0[q * 4 + 0], b0);  fma2(a1[g], wp1[q * 4 + 0], b0);
                fma2(a0[g], wp0[q * 4 + 1], b1);  fma2(a1[g], wp1[q * 4 + 1], b1);
                fma2(a0[g], wp0[q * 4 + 2], b2);  fma2(a1[g], wp1[q * 4 + 2], b2);
                fma2(a0[g], wp0[q * 4 + 3], b3);  fma2(a1[g], wp1[q * 4 + 3], b3);
            }
        }

#pragma unroll
        for (int g = 0; g < 4; g++) {
            if (e0 + g * 8 + el < be) {
                float r0, r1, r2, r3;
                unpack2(a0[g], r0, r1);
                unpack2(a1[g], r2, r3);
                red_add_v4(out + (size_t)uv0[g].y * D + obase, r0, r1, r2, r3);
            }
        }

#pragma unroll
        for (int g = 0; g < 4; g++)
            xs[wid][buf ^ 1][(g * 8 + el) * 5 + qrt] = xn[g];
        __syncwarp();
        buf ^= 1;

#pragma unroll
        for (int g = 0; g < 4; g++) {
            uv0[g] = uv1[g];
            uv1[g] = uv2[g];
        }
    }
}

// relu: read accumulator -> write output; re-zero the 512 segment counters.
__global__ void __launch_bounds__(256)
relu_k(float* __restrict__ out, int n4) {
    const float4* a4 = (const float4*)g_acc;
    float4* o4 = (float4*)out;
    int i = blockIdx.x * 512 + threadIdx.x;
#pragma unroll
    for (int rep = 0; rep < 2; rep++, i += 256) {
        if (i < n4) {
            float4 v = a4[i];
            v.x = fmaxf(v.x, 0.f);
            v.y = fmaxf(v.y, 0.f);
            v.z = fmaxf(v.z, 0.f);
            v.w = fmaxf(v.w, 0.f);
            o4[i] = v;
        }
    }
    if (blockIdx.x == 0) {
        g_bin_fill[threadIdx.x]       = 0;
        g_bin_fill[256 + threadIdx.x] = 0;
    }
}

// ---------------- launcher ----------------
extern "C" void kernel_launch(void* const* d_in, const int* in_sizes, int n_in,
                              void* d_out, int out_size) {
    const float* x    = (const float*)d_in[0];
    const float* W    = (const float*)d_in[1];
    const int*   u    = (const int*)d_in[2];
    const int*   v    = (const int*)d_in[3];
    const int*   widx = (const int*)d_in[4];
    float* out = (float*)d_out;

    const int E = in_sizes[2];

    float* acc;
    cudaGetSymbolAddress((void**)&acc, g_acc);

    scatter_k<<<(E + SC_CHUNK - 1) / SC_CHUNK, SC_THREADS>>>(u, v, widx, E);
    edge_mm_k<<<dim3(2 * N_WEIGHTS, MM_GRID_Y), 256>>>(x, W, acc);
    int n4 = out_size / 4;
    relu_k<<<(n4 + 511) / 512, 256>>>(out, n4);
}